// round 1
// baseline (speedup 1.0000x reference)
#include <cuda_runtime.h>
#include <cuda_bf16.h>
#include <math.h>

// NTXent loss, 2B = 8192, D = 128.
// loss = (1/2B) * sum_i [ log( R_i - e^2 - e^{p_i} ) - q_i ]
//   R_i = sum_j exp(2 * x_i . x_j)    (full row, unmasked)
//   p_i = 2 * x_i . x_{pos(i)}        (positive-pair logit, masked out)
//   q_i = 2 * x_i . x_{col(label_i)}  (picked logit after mask compaction)
// with x_i = e_i / ||e_i||.

#define TWO_B 8192
#define DIM   128

// Scratch (device globals; allocation is forbidden)
__device__ float g_X[TWO_B * DIM];     // normalized embeddings, 4 MB
__device__ float g_part[4][TWO_B];     // per-column-chunk partial row sums
__device__ float g_loss[TWO_B];        // per-row loss

// ---------------------------------------------------------------------------
// 1) Row-normalize: one warp per row.
// ---------------------------------------------------------------------------
__global__ void __launch_bounds__(256) normalize_kernel(const float* __restrict__ E) {
    int warp = threadIdx.x >> 5;
    int lane = threadIdx.x & 31;
    int row  = blockIdx.x * 8 + warp;
    if (row >= TWO_B) return;

    const float4 v = *reinterpret_cast<const float4*>(&E[row * DIM + lane * 4]);
    float ss = v.x * v.x + v.y * v.y + v.z * v.z + v.w * v.w;
    #pragma unroll
    for (int o = 16; o > 0; o >>= 1) ss += __shfl_xor_sync(0xffffffffu, ss, o);
    float inv = rsqrtf(fmaxf(ss, 1e-24f));

    float4 o4;
    o4.x = v.x * inv; o4.y = v.y * inv; o4.z = v.z * inv; o4.w = v.w * inv;
    *reinterpret_cast<float4*>(&g_X[row * DIM + lane * 4]) = o4;
}

// ---------------------------------------------------------------------------
// 2) Fused GEMM + exp + row-sum.
//    Grid: (4 column-chunks of 2048, 64 row-blocks of 128). 256 threads.
//    Each block: 128 rows x 2048 cols, K = 128 (chunks of 32).
//    Thread (tx,ty) in 16x16 layout owns an 8x8 micro-tile.
// ---------------------------------------------------------------------------
__global__ void __launch_bounds__(256) gemm_exp_kernel() {
    __shared__ __align__(16) float As[32][DIM];   // k-major: As[k][m]
    __shared__ __align__(16) float Bs[32][DIM];   // k-major: Bs[k][n]
    __shared__ float red[128][17];                // padded reduce buffer

    const int tid = threadIdx.x;
    const int tx = tid & 15;
    const int ty = tid >> 4;
    const int rowBase  = blockIdx.y * 128;
    const int colBase0 = blockIdx.x * 2048;

    float rowsum[8];
    #pragma unroll
    for (int u = 0; u < 8; ++u) rowsum[u] = 0.f;

    for (int ct = 0; ct < 16; ++ct) {
        const int colBase = colBase0 + ct * 128;
        float acc[8][8];
        #pragma unroll
        for (int u = 0; u < 8; ++u)
            #pragma unroll
            for (int v = 0; v < 8; ++v) acc[u][v] = 0.f;

        #pragma unroll
        for (int kt = 0; kt < 4; ++kt) {
            const int k0 = kt * 32;
            // Cooperative load + transpose into k-major smem.
            // 128 (m) x 32 (k) floats = 1024 float4s, 4 per thread.
            #pragma unroll
            for (int r = 0; r < 4; ++r) {
                int f  = tid + r * 256;        // 0..1023
                int m  = f >> 3;               // 0..127
                int kq = (f & 7) << 2;         // 0,4,...,28
                float4 va = *reinterpret_cast<const float4*>(
                    &g_X[(rowBase + m) * DIM + k0 + kq]);
                As[kq + 0][m] = va.x; As[kq + 1][m] = va.y;
                As[kq + 2][m] = va.z; As[kq + 3][m] = va.w;
                float4 vb = *reinterpret_cast<const float4*>(
                    &g_X[(colBase + m) * DIM + k0 + kq]);
                Bs[kq + 0][m] = vb.x; Bs[kq + 1][m] = vb.y;
                Bs[kq + 2][m] = vb.z; Bs[kq + 3][m] = vb.w;
            }
            __syncthreads();

            #pragma unroll
            for (int k = 0; k < 32; ++k) {
                float a[8], b[8];
                *reinterpret_cast<float4*>(a)     = *reinterpret_cast<const float4*>(&As[k][ty * 8]);
                *reinterpret_cast<float4*>(a + 4) = *reinterpret_cast<const float4*>(&As[k][ty * 8 + 4]);
                *reinterpret_cast<float4*>(b)     = *reinterpret_cast<const float4*>(&Bs[k][tx * 8]);
                *reinterpret_cast<float4*>(b + 4) = *reinterpret_cast<const float4*>(&Bs[k][tx * 8 + 4]);
                #pragma unroll
                for (int u = 0; u < 8; ++u)
                    #pragma unroll
                    for (int v = 0; v < 8; ++v)
                        acc[u][v] = fmaf(a[u], b[v], acc[u][v]);
            }
            __syncthreads();
        }

        // logits = 2*sim; accumulate exp into per-row sums
        #pragma unroll
        for (int u = 0; u < 8; ++u) {
            float s = 0.f;
            #pragma unroll
            for (int v = 0; v < 8; ++v)
                s += __expf(2.0f * acc[u][v]);
            rowsum[u] += s;
        }
    }

    // Reduce 16 threads per row (same ty-group rows, tx varies).
    #pragma unroll
    for (int u = 0; u < 8; ++u)
        red[ty * 8 + u][tx] = rowsum[u];
    __syncthreads();

    if (tid < 128) {
        float s = 0.f;
        #pragma unroll
        for (int j = 0; j < 16; ++j) s += red[tid][j];
        g_part[blockIdx.x][rowBase + tid] = s;
    }
}

// ---------------------------------------------------------------------------
// 3) Per-row finalize: assemble R, subtract masked terms, picked logit.
// ---------------------------------------------------------------------------
__global__ void __launch_bounds__(256) finalize_kernel(const int* __restrict__ labels) {
    int i = blockIdx.x * blockDim.x + threadIdx.x;
    if (i >= TWO_B) return;

    float R = g_part[0][i] + g_part[1][i] + g_part[2][i] + g_part[3][i];

    int pos = (i < TWO_B / 2) ? (i + TWO_B / 2) : (i - TWO_B / 2);
    int a = min(i, pos), b = max(i, pos);
    int l = labels[i];
    int j = l + (l >= a ? 1 : 0);
    j += (j >= b ? 1 : 0);

    const float* xi = g_X + (size_t)i   * DIM;
    const float* xp = g_X + (size_t)pos * DIM;
    const float* xj = g_X + (size_t)j   * DIM;

    float dp = 0.f, dq = 0.f;
    #pragma unroll
    for (int k = 0; k < DIM; k += 4) {
        float4 vi = *reinterpret_cast<const float4*>(&xi[k]);
        float4 vp = *reinterpret_cast<const float4*>(&xp[k]);
        float4 vj = *reinterpret_cast<const float4*>(&xj[k]);
        dp += vi.x * vp.x + vi.y * vp.y + vi.z * vp.z + vi.w * vp.w;
        dq += vi.x * vj.x + vi.y * vj.y + vi.z * vj.z + vi.w * vj.w;
    }
    float p = 2.0f * dp;     // positive-pair logit (masked out of row)
    float q = 2.0f * dq;     // picked logit
    const float E2 = 7.38905609893065f;  // e^2 = exp(diagonal logit)

    float masked = R - E2 - expf(p);
    g_loss[i] = logf(masked) - q;
}

// ---------------------------------------------------------------------------
// 4) Final reduce: mean over 2B rows.
// ---------------------------------------------------------------------------
__global__ void __launch_bounds__(256) reduce_kernel(float* __restrict__ out) {
    __shared__ float sm[256];
    float s = 0.f;
    for (int i = threadIdx.x; i < TWO_B; i += 256) s += g_loss[i];
    sm[threadIdx.x] = s;
    __syncthreads();
    #pragma unroll
    for (int off = 128; off > 0; off >>= 1) {
        if (threadIdx.x < off) sm[threadIdx.x] += sm[threadIdx.x + off];
        __syncthreads();
    }
    if (threadIdx.x == 0) out[0] = sm[0] / (float)TWO_B;
}

// ---------------------------------------------------------------------------
extern "C" void kernel_launch(void* const* d_in, const int* in_sizes, int n_in,
                              void* d_out, int out_size) {
    const float* E      = (const float*)d_in[0];   // [8192,128] fp32
    const int*   labels = (const int*)d_in[1];     // [8192] int32
    float* out = (float*)d_out;

    normalize_kernel<<<TWO_B / 8, 256>>>(E);
    gemm_exp_kernel<<<dim3(4, 64), 256>>>();
    finalize_kernel<<<TWO_B / 256, 256>>>(labels);
    reduce_kernel<<<1, 256>>>(out);
}

// round 3
// speedup vs baseline: 10.7889x; 10.7889x over previous
#include <cuda_runtime.h>
#include <cuda_bf16.h>
#include <math.h>
#include <cstdint>

// NTXent loss, 2B = 8192, D = 128.
// loss = (1/2B) * sum_i [ log( R_i - exp(s_ii) - exp(p_i) ) - q_i ]
//   R_i = sum_j exp(2 * x_i . x_j)  (full row, via bf16 HMMA GEMM + fused exp-rowsum)
//   s_ii, p_i recomputed bf16-consistently; q_i exact fp32.

#define TWO_B 8192
#define DIM   128

__device__ float         g_X [TWO_B * DIM];   // normalized fp32 (finalize path)
__device__ __nv_bfloat16 g_Xh[TWO_B * DIM];   // normalized bf16 (MMA path)
__device__ float         g_part[4][TWO_B];    // per-column-strip row sums
__device__ float         g_loss[TWO_B];

// ---------------------------------------------------------------------------
// helpers
// ---------------------------------------------------------------------------
__device__ __forceinline__ uint32_t smem_u32(const void* p) {
    uint32_t a;
    asm("{ .reg .u64 t; cvta.to.shared.u64 t, %1; cvt.u32.u64 %0, t; }" : "=r"(a) : "l"(p));
    return a;
}
__device__ __forceinline__ void cp16(uint32_t saddr, const void* g) {
    asm volatile("cp.async.cg.shared.global [%0], [%1], 16;" :: "r"(saddr), "l"(g));
}
#define CP_COMMIT() asm volatile("cp.async.commit_group;" ::: "memory")
#define CP_WAIT0()  asm volatile("cp.async.wait_group 0;" ::: "memory")

__device__ __forceinline__ void ldsm4(uint32_t* r, uint32_t addr) {
    asm volatile("ldmatrix.sync.aligned.m8n8.x4.shared.b16 {%0,%1,%2,%3}, [%4];"
                 : "=r"(r[0]), "=r"(r[1]), "=r"(r[2]), "=r"(r[3]) : "r"(addr));
}
__device__ __forceinline__ void mma16816(float* d, const uint32_t* a, uint32_t b0, uint32_t b1) {
    asm volatile("mma.sync.aligned.m16n8k16.row.col.f32.bf16.bf16.f32 "
                 "{%0,%1,%2,%3}, {%4,%5,%6,%7}, {%8,%9}, {%0,%1,%2,%3};"
                 : "+f"(d[0]), "+f"(d[1]), "+f"(d[2]), "+f"(d[3])
                 : "r"(a[0]), "r"(a[1]), "r"(a[2]), "r"(a[3]), "r"(b0), "r"(b1));
}
__device__ __forceinline__ float ex2(float x) {
    float y; asm("ex2.approx.ftz.f32 %0, %1;" : "=f"(y) : "f"(x)); return y;
}

// ---------------------------------------------------------------------------
// 1) Row-normalize -> fp32 + bf16 copies. One warp per row.
// ---------------------------------------------------------------------------
__global__ void __launch_bounds__(256) normalize_kernel(const float* __restrict__ E) {
    int warp = threadIdx.x >> 5, lane = threadIdx.x & 31;
    int row = blockIdx.x * 8 + warp;
    const float4 v = *reinterpret_cast<const float4*>(&E[row * DIM + lane * 4]);
    float ss = v.x * v.x + v.y * v.y + v.z * v.z + v.w * v.w;
    #pragma unroll
    for (int o = 16; o > 0; o >>= 1) ss += __shfl_xor_sync(0xffffffffu, ss, o);
    float inv = rsqrtf(fmaxf(ss, 1e-24f));
    float4 o4 = {v.x * inv, v.y * inv, v.z * inv, v.w * inv};
    *reinterpret_cast<float4*>(&g_X[row * DIM + lane * 4]) = o4;
    __nv_bfloat162 h0 = __float22bfloat162_rn(make_float2(o4.x, o4.y));
    __nv_bfloat162 h1 = __float22bfloat162_rn(make_float2(o4.z, o4.w));
    uint2 pk = { *reinterpret_cast<uint32_t*>(&h0), *reinterpret_cast<uint32_t*>(&h1) };
    *reinterpret_cast<uint2*>(&g_Xh[row * DIM + lane * 4]) = pk;
}

// ---------------------------------------------------------------------------
// 2) bf16 HMMA GEMM + exp + row-sum.
//    Grid (4, 64): blockIdx.x = 2048-col strip, blockIdx.y = 128-row block.
//    256 threads = 8 warps as (wm 0..3) x (wn 0..1); warp tile 32x64.
//    16 chunks of 128 cols; B double-buffered with cp.async.
// ---------------------------------------------------------------------------
#define SROWB   272                      // smem row stride bytes (17*16)
#define TILE_B  (128 * SROWB)            // 34816
#define SM_A    0
#define SM_B0   TILE_B
#define SM_B1   (2 * TILE_B)
#define SM_RED  (3 * TILE_B)             // float sred[2][128]
#define SM_TOT  (SM_RED + 2 * 128 * 4)
#define NCHUNK  16

__global__ void __launch_bounds__(256, 2) gemm_mma_kernel() {
    extern __shared__ __align__(16) char smem[];
    const uint32_t sb = smem_u32(smem);
    const int tid  = threadIdx.x;
    const int lane = tid & 31;
    const int warp = tid >> 5;
    const int wm = warp >> 1;            // 0..3  (row group of 32)
    const int wn = warp & 1;             // 0..1  (col group of 64)
    const int rowBase  = blockIdx.y * 128;
    const int colBase0 = blockIdx.x * 2048;

    const char* __restrict__ Xb = reinterpret_cast<const char*>(g_Xh);

    // ---- async load A tile (128 rows x 256B) + B chunk 0 ----
    {
        #pragma unroll
        for (int i = 0; i < 8; ++i) {
            int f = tid + i * 256;              // 0..2047
            int r = f >> 4, c = (f & 15) << 4;  // row, byte col
            cp16(sb + SM_A + r * SROWB + c, Xb + (size_t)(rowBase + r) * 256 + c);
            cp16(sb + SM_B0 + r * SROWB + c, Xb + (size_t)(colBase0 + r) * 256 + c);
        }
        CP_COMMIT();
    }

    // per-lane ldmatrix base offsets (bytes)
    const uint32_t aBase = sb + SM_A + (uint32_t)(wm * 32 + (lane & 15)) * SROWB + ((lane >> 4) << 4);
    const uint32_t bOff  = (uint32_t)(wn * 64 + (lane & 15)) * SROWB + ((lane >> 4) << 4);

    float acc[2][8][4];
    float rowsum[4] = {0.f, 0.f, 0.f, 0.f};
    const float C2 = 2.8853900817779268f;   // 2*log2(e)

    for (int c = 0; c < NCHUNK; ++c) {
        CP_WAIT0();
        __syncthreads();
        // prefetch next B chunk into the other buffer
        if (c + 1 < NCHUNK) {
            const uint32_t bb = sb + (((c + 1) & 1) ? SM_B1 : SM_B0);
            const int colBase = colBase0 + (c + 1) * 128;
            #pragma unroll
            for (int i = 0; i < 8; ++i) {
                int f = tid + i * 256;
                int r = f >> 4, cc = (f & 15) << 4;
                cp16(bb + r * SROWB + cc, Xb + (size_t)(colBase + r) * 256 + cc);
            }
            CP_COMMIT();
        }

        const uint32_t bBase = sb + ((c & 1) ? SM_B1 : SM_B0) + bOff;

        #pragma unroll
        for (int m = 0; m < 2; ++m)
            #pragma unroll
            for (int n = 0; n < 8; ++n)
                #pragma unroll
                for (int u = 0; u < 4; ++u) acc[m][n][u] = 0.f;

        #pragma unroll
        for (int ks = 0; ks < 8; ++ks) {
            uint32_t a[2][4], b[4][4];
            #pragma unroll
            for (int m = 0; m < 2; ++m)
                ldsm4(a[m], aBase + m * (16 * SROWB) + ks * 32);
            #pragma unroll
            for (int n4 = 0; n4 < 4; ++n4)
                ldsm4(b[n4], bBase + n4 * (16 * SROWB) + ks * 32);
            #pragma unroll
            for (int m = 0; m < 2; ++m)
                #pragma unroll
                for (int n4 = 0; n4 < 4; ++n4) {
                    mma16816(acc[m][n4 * 2 + 0], a[m], b[n4][0], b[n4][2]);
                    mma16816(acc[m][n4 * 2 + 1], a[m], b[n4][1], b[n4][3]);
                }
        }

        // fused epilogue: rowsum += exp(2*sim)
        #pragma unroll
        for (int m = 0; m < 2; ++m) {
            float s0 = 0.f, s1 = 0.f;
            #pragma unroll
            for (int n = 0; n < 8; ++n) {
                s0 += ex2(acc[m][n][0] * C2) + ex2(acc[m][n][1] * C2);
                s1 += ex2(acc[m][n][2] * C2) + ex2(acc[m][n][3] * C2);
            }
            rowsum[m * 2 + 0] += s0;
            rowsum[m * 2 + 1] += s1;
        }
    }

    // deterministic reduction: lanes sharing a row (lane%4) first
    #pragma unroll
    for (int u = 0; u < 4; ++u) {
        rowsum[u] += __shfl_xor_sync(0xffffffffu, rowsum[u], 1);
        rowsum[u] += __shfl_xor_sync(0xffffffffu, rowsum[u], 2);
    }
    float* sred = reinterpret_cast<float*>(smem + SM_RED);  // [2][128]
    __syncthreads();
    if ((lane & 3) == 0) {
        #pragma unroll
        for (int u = 0; u < 4; ++u) {
            int r = wm * 32 + (u >> 1) * 16 + (u & 1) * 8 + (lane >> 2);
            sred[wn * 128 + r] = rowsum[u];
        }
    }
    __syncthreads();
    if (tid < 128)
        g_part[blockIdx.x][rowBase + tid] = sred[tid] + sred[128 + tid];
}

// ---------------------------------------------------------------------------
// 3) Per-row finalize.
// ---------------------------------------------------------------------------
__global__ void __launch_bounds__(256) finalize_kernel(const int* __restrict__ labels) {
    int i = blockIdx.x * blockDim.x + threadIdx.x;
    if (i >= TWO_B) return;

    float R = g_part[0][i] + g_part[1][i] + g_part[2][i] + g_part[3][i];

    int pos = (i < TWO_B / 2) ? (i + TWO_B / 2) : (i - TWO_B / 2);
    int a = min(i, pos), b = max(i, pos);
    int l = labels[i];
    int j = l + (l >= a ? 1 : 0);
    j += (j >= b ? 1 : 0);

    const float* xi = g_X + (size_t)i * DIM;
    const float* xj = g_X + (size_t)j * DIM;
    float dq = 0.f;
    #pragma unroll
    for (int k = 0; k < DIM; k += 4) {
        float4 vi = *reinterpret_cast<const float4*>(&xi[k]);
        float4 vj = *reinterpret_cast<const float4*>(&xj[k]);
        dq += vi.x * vj.x + vi.y * vj.y + vi.z * vj.z + vi.w * vj.w;
    }
    // bf16-consistent diagonal + positive-pair terms (same inputs the GEMM saw)
    float dii = 0.f, dpp = 0.f;
    const __nv_bfloat16* hi = g_Xh + (size_t)i   * DIM;
    const __nv_bfloat16* hp = g_Xh + (size_t)pos * DIM;
    #pragma unroll
    for (int k = 0; k < DIM; k += 2) {
        float2 a2 = __bfloat1622float2(*reinterpret_cast<const __nv_bfloat162*>(&hi[k]));
        float2 b2 = __bfloat1622float2(*reinterpret_cast<const __nv_bfloat162*>(&hp[k]));
        dii += a2.x * a2.x + a2.y * a2.y;
        dpp += a2.x * b2.x + a2.y * b2.y;
    }

    float masked = R - __expf(2.f * dii) - __expf(2.f * dpp);
    g_loss[i] = logf(masked) - 2.0f * dq;
}

// ---------------------------------------------------------------------------
// 4) Final reduce: mean over 2B rows.
// ---------------------------------------------------------------------------
__global__ void __launch_bounds__(256) reduce_kernel(float* __restrict__ out) {
    __shared__ float sm[256];
    float s = 0.f;
    for (int i = threadIdx.x; i < TWO_B; i += 256) s += g_loss[i];
    sm[threadIdx.x] = s;
    __syncthreads();
    #pragma unroll
    for (int off = 128; off > 0; off >>= 1) {
        if (threadIdx.x < off) sm[threadIdx.x] += sm[threadIdx.x + off];
        __syncthreads();
    }
    if (threadIdx.x == 0) out[0] = sm[0] / (float)TWO_B;
}

// ---------------------------------------------------------------------------
extern "C" void kernel_launch(void* const* d_in, const int* in_sizes, int n_in,
                              void* d_out, int out_size) {
    const float* E      = (const float*)d_in[0];
    const int*   labels = (const int*)d_in[1];
    float* out = (float*)d_out;

    cudaFuncSetAttribute(gemm_mma_kernel,
                         cudaFuncAttributeMaxDynamicSharedMemorySize, SM_TOT);

    normalize_kernel<<<TWO_B / 8, 256>>>(E);
    gemm_mma_kernel<<<dim3(4, 64), 256, SM_TOT>>>();
    finalize_kernel<<<TWO_B / 256, 256>>>(labels);
    reduce_kernel<<<1, 256>>>(out);
}

// round 4
// speedup vs baseline: 13.1258x; 1.2166x over previous
#include <cuda_runtime.h>
#include <cuda_bf16.h>
#include <math.h>
#include <cstdint>

// NTXent loss, 2B = 8192, D = 128.
// loss = (1/2B) * sum_i [ log( R_i - exp(s_ii) - exp(p_i) ) - q_i ]
// R_i via symmetric bf16 HMMA GEMM: only upper-triangle 128x128 blocks are
// computed; each block contributes row-sums (rows of I) AND column-sums
// (rows of J) of exp(2*sim). Deterministic partials, no atomics.

#define TWO_B   8192
#define DIM     128
#define NBLK    64            // 8192 / 128
#define NPAIRS  2080          // NBLK*(NBLK+1)/2

__device__ float         g_X [TWO_B * DIM];     // normalized fp32 (finalize)
__device__ __nv_bfloat16 g_Xh[TWO_B * DIM];     // normalized bf16 (MMA)
__device__ float         g_part[NBLK][TWO_B];   // [slot][row] partial row sums
__device__ float         g_loss[TWO_B];

// ---------------------------------------------------------------------------
// helpers
// ---------------------------------------------------------------------------
__device__ __forceinline__ uint32_t smem_u32(const void* p) {
    uint32_t a;
    asm("{ .reg .u64 t; cvta.to.shared.u64 t, %1; cvt.u32.u64 %0, t; }" : "=r"(a) : "l"(p));
    return a;
}
__device__ __forceinline__ void cp16(uint32_t saddr, const void* g) {
    asm volatile("cp.async.cg.shared.global [%0], [%1], 16;" :: "r"(saddr), "l"(g));
}
#define CP_COMMIT() asm volatile("cp.async.commit_group;" ::: "memory")
#define CP_WAIT0()  asm volatile("cp.async.wait_group 0;" ::: "memory")

__device__ __forceinline__ void ldsm4(uint32_t* r, uint32_t addr) {
    asm volatile("ldmatrix.sync.aligned.m8n8.x4.shared.b16 {%0,%1,%2,%3}, [%4];"
                 : "=r"(r[0]), "=r"(r[1]), "=r"(r[2]), "=r"(r[3]) : "r"(addr));
}
__device__ __forceinline__ void mma16816(float* d, const uint32_t* a, uint32_t b0, uint32_t b1) {
    asm volatile("mma.sync.aligned.m16n8k16.row.col.f32.bf16.bf16.f32 "
                 "{%0,%1,%2,%3}, {%4,%5,%6,%7}, {%8,%9}, {%0,%1,%2,%3};"
                 : "+f"(d[0]), "+f"(d[1]), "+f"(d[2]), "+f"(d[3])
                 : "r"(a[0]), "r"(a[1]), "r"(a[2]), "r"(a[3]), "r"(b0), "r"(b1));
}
__device__ __forceinline__ float ex2(float x) {
    float y; asm("ex2.approx.ftz.f32 %0, %1;" : "=f"(y) : "f"(x)); return y;
}

// ---------------------------------------------------------------------------
// 1) Row-normalize -> fp32 + bf16 copies. One warp per row.
// ---------------------------------------------------------------------------
__global__ void __launch_bounds__(256) normalize_kernel(const float* __restrict__ E) {
    int warp = threadIdx.x >> 5, lane = threadIdx.x & 31;
    int row = blockIdx.x * 8 + warp;
    const float4 v = *reinterpret_cast<const float4*>(&E[row * DIM + lane * 4]);
    float ss = v.x * v.x + v.y * v.y + v.z * v.z + v.w * v.w;
    #pragma unroll
    for (int o = 16; o > 0; o >>= 1) ss += __shfl_xor_sync(0xffffffffu, ss, o);
    float inv = rsqrtf(fmaxf(ss, 1e-24f));
    float4 o4 = {v.x * inv, v.y * inv, v.z * inv, v.w * inv};
    *reinterpret_cast<float4*>(&g_X[row * DIM + lane * 4]) = o4;
    __nv_bfloat162 h0 = __float22bfloat162_rn(make_float2(o4.x, o4.y));
    __nv_bfloat162 h1 = __float22bfloat162_rn(make_float2(o4.z, o4.w));
    uint2 pk = { *reinterpret_cast<uint32_t*>(&h0), *reinterpret_cast<uint32_t*>(&h1) };
    *reinterpret_cast<uint2*>(&g_Xh[row * DIM + lane * 4]) = pk;
}

// ---------------------------------------------------------------------------
// 2) Symmetric HMMA GEMM + exp, row-sums AND column-sums per tile.
//    Grid: 2080 blocks = upper-triangle (I<=J) of 64x64 block grid.
//    256 threads = 8 warps as (wm 0..3) x (wn 0..1); warp tile 32x64; K=128.
// ---------------------------------------------------------------------------
#define SROWB   272                       // smem row stride bytes (17*16)
#define TILE_B  (128 * SROWB)             // 34816
#define SM_A    0
#define SM_B    TILE_B
#define SM_RED  (2 * TILE_B)              // rowred[2][128] then colred[4][128]
#define SM_COL  (SM_RED + 2 * 128 * 4)
#define SM_TOT  (SM_COL + 4 * 128 * 4)

__global__ void __launch_bounds__(256, 2) gemm_sym_kernel() {
    extern __shared__ __align__(16) char smem[];
    const uint32_t sb = smem_u32(smem);
    const int tid  = threadIdx.x;
    const int lane = tid & 31;
    const int warp = tid >> 5;
    const int wm = warp >> 1;             // 0..3
    const int wn = warp & 1;              // 0..1

    // map linear pair index -> (I, J), I <= J
    const int t = blockIdx.x;
    int I = (int)((129.0 - sqrt(129.0 * 129.0 - 8.0 * (double)t)) * 0.5);
    I = max(0, min(63, I));
    while (I * 64 - (I * (I - 1)) / 2 > t) --I;
    while ((I + 1) * 64 - ((I + 1) * I) / 2 <= t) ++I;
    const int J = I + (t - (I * 64 - (I * (I - 1)) / 2));
    const int rowBase = I * 128;
    const int colBase = J * 128;

    const char* __restrict__ Xb = reinterpret_cast<const char*>(g_Xh);

    // async load A (rows of I) and B (rows of J): 128 x 256B each
    #pragma unroll
    for (int i = 0; i < 8; ++i) {
        int f = tid + i * 256;               // 0..2047
        int r = f >> 4, c = (f & 15) << 4;
        cp16(sb + SM_A + r * SROWB + c, Xb + (size_t)(rowBase + r) * 256 + c);
        cp16(sb + SM_B + r * SROWB + c, Xb + (size_t)(colBase + r) * 256 + c);
    }
    CP_COMMIT();

    const uint32_t aBase = sb + SM_A + (uint32_t)(wm * 32 + (lane & 15)) * SROWB + ((lane >> 4) << 4);
    const uint32_t bBase = sb + SM_B + (uint32_t)(wn * 64 + (lane & 15)) * SROWB + ((lane >> 4) << 4);

    float acc[2][8][4];
    #pragma unroll
    for (int m = 0; m < 2; ++m)
        #pragma unroll
        for (int n = 0; n < 8; ++n)
            #pragma unroll
            for (int u = 0; u < 4; ++u) acc[m][n][u] = 0.f;

    CP_WAIT0();
    __syncthreads();

    #pragma unroll
    for (int ks = 0; ks < 8; ++ks) {
        uint32_t a[2][4], b[4][4];
        #pragma unroll
        for (int m = 0; m < 2; ++m)
            ldsm4(a[m], aBase + m * (16 * SROWB) + ks * 32);
        #pragma unroll
        for (int n4 = 0; n4 < 4; ++n4)
            ldsm4(b[n4], bBase + n4 * (16 * SROWB) + ks * 32);
        #pragma unroll
        for (int m = 0; m < 2; ++m)
            #pragma unroll
            for (int n4 = 0; n4 < 4; ++n4) {
                mma16816(acc[m][n4 * 2 + 0], a[m], b[n4][0], b[n4][2]);
                mma16816(acc[m][n4 * 2 + 1], a[m], b[n4][1], b[n4][3]);
            }
    }

    // epilogue: e = exp(2*sim); accumulate row sums and column sums
    const float C2 = 2.8853900817779268f;   // 2*log2(e)
    float rs[4] = {0.f, 0.f, 0.f, 0.f};
    float cs[8][2];
    #pragma unroll
    for (int n = 0; n < 8; ++n) { cs[n][0] = 0.f; cs[n][1] = 0.f; }

    #pragma unroll
    for (int m = 0; m < 2; ++m)
        #pragma unroll
        for (int n = 0; n < 8; ++n)
            #pragma unroll
            for (int u = 0; u < 4; ++u) {
                float e = ex2(acc[m][n][u] * C2);
                rs[m * 2 + (u >> 1)] += e;
                cs[n][u & 1] += e;
            }

    // row sums: combine the 4 lanes sharing a row (lane&3)
    #pragma unroll
    for (int u = 0; u < 4; ++u) {
        rs[u] += __shfl_xor_sync(0xffffffffu, rs[u], 1);
        rs[u] += __shfl_xor_sync(0xffffffffu, rs[u], 2);
    }
    // column sums: combine the 8 row-groups (lane>>2)
    #pragma unroll
    for (int n = 0; n < 8; ++n)
        #pragma unroll
        for (int b = 0; b < 2; ++b) {
            cs[n][b] += __shfl_xor_sync(0xffffffffu, cs[n][b], 4);
            cs[n][b] += __shfl_xor_sync(0xffffffffu, cs[n][b], 8);
            cs[n][b] += __shfl_xor_sync(0xffffffffu, cs[n][b], 16);
        }

    float* rowred = reinterpret_cast<float*>(smem + SM_RED);   // [2][128]
    float* colred = reinterpret_cast<float*>(smem + SM_COL);   // [4][128]
    __syncthreads();   // all reads of A/B done; reuse red region safely

    if ((lane & 3) == 0) {
        #pragma unroll
        for (int u = 0; u < 4; ++u) {
            int r = wm * 32 + (u >> 1) * 16 + (u & 1) * 8 + (lane >> 2);
            rowred[wn * 128 + r] = rs[u];
        }
    }
    if (lane < 4) {
        #pragma unroll
        for (int n = 0; n < 8; ++n)
            #pragma unroll
            for (int b = 0; b < 2; ++b) {
                int c = wn * 64 + (n >> 1) * 16 + (n & 1) * 8 + lane * 2 + b;
                colred[wm * 128 + c] = cs[n][b];
            }
    }
    __syncthreads();

    if (tid < 128) {
        float rt = rowred[tid] + rowred[128 + tid];
        g_part[J][rowBase + tid] = rt;                 // rows of I, slot J
        if (I != J) {
            float ct = colred[tid] + colred[128 + tid] +
                       colred[256 + tid] + colred[384 + tid];
            g_part[I][colBase + tid] = ct;             // rows of J, slot I
        }
    }
}

// ---------------------------------------------------------------------------
// 3) Per-row finalize.
// ---------------------------------------------------------------------------
__global__ void __launch_bounds__(256) finalize_kernel(const int* __restrict__ labels) {
    int i = blockIdx.x * blockDim.x + threadIdx.x;
    if (i >= TWO_B) return;

    float R = 0.f;
    #pragma unroll 8
    for (int s = 0; s < NBLK; ++s) R += g_part[s][i];

    int pos = (i < TWO_B / 2) ? (i + TWO_B / 2) : (i - TWO_B / 2);
    int a = min(i, pos), b = max(i, pos);
    int l = labels[i];
    int j = l + (l >= a ? 1 : 0);
    j += (j >= b ? 1 : 0);

    const float* xi = g_X + (size_t)i * DIM;
    const float* xj = g_X + (size_t)j * DIM;
    float dq = 0.f;
    #pragma unroll
    for (int k = 0; k < DIM; k += 4) {
        float4 vi = *reinterpret_cast<const float4*>(&xi[k]);
        float4 vj = *reinterpret_cast<const float4*>(&xj[k]);
        dq += vi.x * vj.x + vi.y * vj.y + vi.z * vj.z + vi.w * vj.w;
    }
    // bf16-consistent diagonal + positive-pair terms (same inputs the GEMM saw)
    float dii = 0.f, dpp = 0.f;
    const __nv_bfloat16* hi = g_Xh + (size_t)i   * DIM;
    const __nv_bfloat16* hp = g_Xh + (size_t)pos * DIM;
    #pragma unroll
    for (int k = 0; k < DIM; k += 2) {
        float2 a2 = __bfloat1622float2(*reinterpret_cast<const __nv_bfloat162*>(&hi[k]));
        float2 b2 = __bfloat1622float2(*reinterpret_cast<const __nv_bfloat162*>(&hp[k]));
        dii += a2.x * a2.x + a2.y * a2.y;
        dpp += a2.x * b2.x + a2.y * b2.y;
    }

    float masked = R - __expf(2.f * dii) - __expf(2.f * dpp);
    g_loss[i] = logf(masked) - 2.0f * dq;
}

// ---------------------------------------------------------------------------
// 4) Final reduce: mean over 2B rows.
// ---------------------------------------------------------------------------
__global__ void __launch_bounds__(256) reduce_kernel(float* __restrict__ out) {
    __shared__ float sm[256];
    float s = 0.f;
    for (int i = threadIdx.x; i < TWO_B; i += 256) s += g_loss[i];
    sm[threadIdx.x] = s;
    __syncthreads();
    #pragma unroll
    for (int off = 128; off > 0; off >>= 1) {
        if (threadIdx.x < off) sm[threadIdx.x] += sm[threadIdx.x + off];
        __syncthreads();
    }
    if (threadIdx.x == 0) out[0] = sm[0] / (float)TWO_B;
}

// ---------------------------------------------------------------------------
extern "C" void kernel_launch(void* const* d_in, const int* in_sizes, int n_in,
                              void* d_out, int out_size) {
    const float* E      = (const float*)d_in[0];
    const int*   labels = (const int*)d_in[1];
    float* out = (float*)d_out;

    cudaFuncSetAttribute(gemm_sym_kernel,
                         cudaFuncAttributeMaxDynamicSharedMemorySize, SM_TOT);

    normalize_kernel<<<TWO_B / 8, 256>>>(E);
    gemm_sym_kernel<<<NPAIRS, 256, SM_TOT>>>();
    finalize_kernel<<<TWO_B / 256, 256>>>(labels);
    reduce_kernel<<<1, 256>>>(out);
}

// round 8
// speedup vs baseline: 14.1870x; 1.0809x over previous
#include <cuda_runtime.h>
#include <cuda_bf16.h>
#include <math.h>
#include <cstdint>

// NTXent loss, 2B = 8192, D = 128.
// Symmetric bf16 HMMA GEMM over upper-triangle 128x128 blocks, strip-mined:
// CTA = (row block I, column octet c), processing tiles J in [max(8c,I), 8c+7].
// Each tile contributes row-sums (rows of I, accumulated across the strip) and
// column-sums (rows of J) of exp(2*sim). Deterministic partials, no atomics.

#define TWO_B   8192
#define DIM     128
#define NBLK    64
#define NCTA    288           // sum over octets o: (8-o)*8
#define NSLOT   72            // 8 row-sum slots + 64 col-sum slots

__device__ float         g_X [TWO_B * DIM];     // normalized fp32 (finalize)
__device__ __nv_bfloat16 g_Xh[TWO_B * DIM];     // normalized bf16 (MMA)
__device__ float         g_part[NSLOT][TWO_B];  // [slot][row] partials (unused stay 0)
__device__ float         g_loss[TWO_B];

// ---------------------------------------------------------------------------
// helpers
// ---------------------------------------------------------------------------
__device__ __forceinline__ uint32_t smem_u32(const void* p) {
    uint32_t a;
    asm("{ .reg .u64 t; cvta.to.shared.u64 t, %1; cvt.u32.u64 %0, t; }" : "=r"(a) : "l"(p));
    return a;
}
__device__ __forceinline__ void cp16(uint32_t saddr, const void* g) {
    asm volatile("cp.async.cg.shared.global [%0], [%1], 16;" :: "r"(saddr), "l"(g));
}
#define CP_COMMIT() asm volatile("cp.async.commit_group;" ::: "memory")
#define CP_WAIT0()  asm volatile("cp.async.wait_group 0;" ::: "memory")

__device__ __forceinline__ void ldsm4(uint32_t* r, uint32_t addr) {
    asm volatile("ldmatrix.sync.aligned.m8n8.x4.shared.b16 {%0,%1,%2,%3}, [%4];"
                 : "=r"(r[0]), "=r"(r[1]), "=r"(r[2]), "=r"(r[3]) : "r"(addr));
}
__device__ __forceinline__ void mma16816(float* d, const uint32_t* a, uint32_t b0, uint32_t b1) {
    asm volatile("mma.sync.aligned.m16n8k16.row.col.f32.bf16.bf16.f32 "
                 "{%0,%1,%2,%3}, {%4,%5,%6,%7}, {%8,%9}, {%0,%1,%2,%3};"
                 : "+f"(d[0]), "+f"(d[1]), "+f"(d[2]), "+f"(d[3])
                 : "r"(a[0]), "r"(a[1]), "r"(a[2]), "r"(a[3]), "r"(b0), "r"(b1));
}
__device__ __forceinline__ float ex2(float x) {
    float y; asm("ex2.approx.ftz.f32 %0, %1;" : "=f"(y) : "f"(x)); return y;
}

// ---------------------------------------------------------------------------
// 1) Row-normalize -> fp32 + bf16 copies. One warp per row.
// ---------------------------------------------------------------------------
__global__ void __launch_bounds__(256) normalize_kernel(const float* __restrict__ E) {
    int warp = threadIdx.x >> 5, lane = threadIdx.x & 31;
    int row = blockIdx.x * 8 + warp;
    const float4 v = *reinterpret_cast<const float4*>(&E[row * DIM + lane * 4]);
    float ss = v.x * v.x + v.y * v.y + v.z * v.z + v.w * v.w;
    #pragma unroll
    for (int o = 16; o > 0; o >>= 1) ss += __shfl_xor_sync(0xffffffffu, ss, o);
    float inv = rsqrtf(fmaxf(ss, 1e-24f));
    float4 o4 = {v.x * inv, v.y * inv, v.z * inv, v.w * inv};
    *reinterpret_cast<float4*>(&g_X[row * DIM + lane * 4]) = o4;
    __nv_bfloat162 h0 = __float22bfloat162_rn(make_float2(o4.x, o4.y));
    __nv_bfloat162 h1 = __float22bfloat162_rn(make_float2(o4.z, o4.w));
    uint2 pk = { *reinterpret_cast<uint32_t*>(&h0), *reinterpret_cast<uint32_t*>(&h1) };
    *reinterpret_cast<uint2*>(&g_Xh[row * DIM + lane * 4]) = pk;
}

// ---------------------------------------------------------------------------
// 2) Strip-mined symmetric HMMA GEMM + exp row/col sums.
//    256 threads = 8 warps (wm 0..3 x wn 0..1); warp tile 32x64; K=128.
// ---------------------------------------------------------------------------
#define SROWB   272                        // smem row stride (17*16 B)
#define TILE_B  (128 * SROWB)              // 34816
#define SM_A    0
#define SM_B0   TILE_B
#define SM_B1   (2 * TILE_B)
#define SM_RED  (3 * TILE_B)               // colred[4][128] / rowred[2][128]
#define SM_TOT  (SM_RED + 4 * 128 * 4)

__global__ void __launch_bounds__(256, 2) gemm_sym_kernel() {
    extern __shared__ __align__(16) char smem[];
    const uint32_t sb = smem_u32(smem);
    const int tid  = threadIdx.x;
    const int lane = tid & 31;
    const int warp = tid >> 5;
    const int wm = warp >> 1;              // 0..3
    const int wn = warp & 1;               // 0..1

    // decode blockIdx -> (I, c): octet o of I, chunks c = o..7
    int t = blockIdx.x, o = 0;
    for (;;) { int n = (8 - o) * 8; if (t < n) break; t -= n; ++o; }
    const int c  = o + (t >> 3);
    const int I  = 8 * o + (t & 7);
    const int J0 = max(8 * c, I);
    const int L  = 8 * c + 8 - J0;         // strip length (1..8)
    const int rowBase = I * 128;

    const char* __restrict__ Xb = reinterpret_cast<const char*>(g_Xh);

    // cooperative 32KB tile load (128 rows x 256B)
    auto loadTile = [&](uint32_t dst, int gRow) {
        #pragma unroll
        for (int i = 0; i < 8; ++i) {
            int f = tid + i * 256;
            int r = f >> 4, cc = (f & 15) << 4;
            cp16(dst + r * SROWB + cc, Xb + (size_t)(gRow + r) * 256 + cc);
        }
    };

    loadTile(sb + SM_A, rowBase);
    loadTile(sb + SM_B0, J0 * 128);
    CP_COMMIT();

    const uint32_t aBase = sb + SM_A + (uint32_t)(wm * 32 + (lane & 15)) * SROWB + ((lane >> 4) << 4);
    const uint32_t bOff  = (uint32_t)(wn * 64 + (lane & 15)) * SROWB + ((lane >> 4) << 4);

    const float C2 = 2.8853900817779268f;  // 2*log2(e)
    float rs[4] = {0.f, 0.f, 0.f, 0.f};    // strip-accumulated row sums
    float* colred = reinterpret_cast<float*>(smem + SM_RED);   // [4][128]

    for (int k = 0; k < L; ++k) {
        const int J = J0 + k;
        CP_WAIT0();
        __syncthreads();   // B(k) resident; prev tile's colred reads done

        if (k + 1 < L) {
            loadTile(sb + (((k + 1) & 1) ? SM_B1 : SM_B0), (J + 1) * 128);
            CP_COMMIT();
        }

        const uint32_t bBase = sb + ((k & 1) ? SM_B1 : SM_B0) + bOff;

        float acc[2][8][4];
        #pragma unroll
        for (int m = 0; m < 2; ++m)
            #pragma unroll
            for (int n = 0; n < 8; ++n)
                #pragma unroll
                for (int u = 0; u < 4; ++u) acc[m][n][u] = 0.f;

        #pragma unroll
        for (int ks = 0; ks < 8; ++ks) {
            uint32_t a[2][4], b[4][4];
            #pragma unroll
            for (int m = 0; m < 2; ++m)
                ldsm4(a[m], aBase + m * (16 * SROWB) + ks * 32);
            #pragma unroll
            for (int n4 = 0; n4 < 4; ++n4)
                ldsm4(b[n4], bBase + n4 * (16 * SROWB) + ks * 32);
            #pragma unroll
            for (int m = 0; m < 2; ++m)
                #pragma unroll
                for (int n4 = 0; n4 < 4; ++n4) {
                    mma16816(acc[m][n4 * 2 + 0], a[m], b[n4][0], b[n4][2]);
                    mma16816(acc[m][n4 * 2 + 1], a[m], b[n4][1], b[n4][3]);
                }
        }

        // epilogue: e = exp(2*sim); rows -> rs (strip accum), cols -> cs
        float cs[8][2];
        #pragma unroll
        for (int n = 0; n < 8; ++n) { cs[n][0] = 0.f; cs[n][1] = 0.f; }

        #pragma unroll
        for (int m = 0; m < 2; ++m)
            #pragma unroll
            for (int n = 0; n < 8; ++n)
                #pragma unroll
                for (int u = 0; u < 4; ++u) {
                    float e = ex2(acc[m][n][u] * C2);
                    rs[m * 2 + (u >> 1)] += e;
                    cs[n][u & 1] += e;
                }

        if (J != I) {
            // column sums: combine the 8 row-groups within each warp
            #pragma unroll
            for (int n = 0; n < 8; ++n)
                #pragma unroll
                for (int b = 0; b < 2; ++b) {
                    cs[n][b] += __shfl_xor_sync(0xffffffffu, cs[n][b], 4);
                    cs[n][b] += __shfl_xor_sync(0xffffffffu, cs[n][b], 8);
                    cs[n][b] += __shfl_xor_sync(0xffffffffu, cs[n][b], 16);
                }
            if (lane < 4) {
                #pragma unroll
                for (int n = 0; n < 8; ++n)
                    #pragma unroll
                    for (int b = 0; b < 2; ++b) {
                        int cc = wn * 64 + (n >> 1) * 16 + (n & 1) * 8 + lane * 2 + b;
                        colred[wm * 128 + cc] = cs[n][b];
                    }
            }
            __syncthreads();
            if (tid < 128) {
                float ct = colred[tid] + colred[128 + tid] +
                           colred[256 + tid] + colred[384 + tid];
                g_part[8 + I][J * 128 + tid] = ct;
            }
        } else {
            __syncthreads();   // keep barrier count uniform with the other path
        }
    }

    // strip row sums: lanes sharing a row, then cross-warp combine
    #pragma unroll
    for (int u = 0; u < 4; ++u) {
        rs[u] += __shfl_xor_sync(0xffffffffu, rs[u], 1);
        rs[u] += __shfl_xor_sync(0xffffffffu, rs[u], 2);
    }
    float* rowred = reinterpret_cast<float*>(smem + SM_RED);   // [2][128]
    __syncthreads();
    if ((lane & 3) == 0) {
        #pragma unroll
        for (int u = 0; u < 4; ++u) {
            int r = wm * 32 + (u >> 1) * 16 + (u & 1) * 8 + (lane >> 2);
            rowred[wn * 128 + r] = rs[u];
        }
    }
    __syncthreads();
    if (tid < 128)
        g_part[c][rowBase + tid] = rowred[tid] + rowred[128 + tid];
}

// ---------------------------------------------------------------------------
// 3) Per-row finalize.
// ---------------------------------------------------------------------------
__global__ void __launch_bounds__(256) finalize_kernel(const int* __restrict__ labels) {
    int i = blockIdx.x * blockDim.x + threadIdx.x;
    if (i >= TWO_B) return;

    float R = 0.f;
    #pragma unroll 8
    for (int s = 0; s < NSLOT; ++s) R += g_part[s][i];

    int pos = (i < TWO_B / 2) ? (i + TWO_B / 2) : (i - TWO_B / 2);
    int a = min(i, pos), b = max(i, pos);
    int l = labels[i];
    int j = l + (l >= a ? 1 : 0);
    j += (j >= b ? 1 : 0);

    const float* xi = g_X + (size_t)i * DIM;
    const float* xj = g_X + (size_t)j * DIM;
    float dq = 0.f;
    #pragma unroll
    for (int k = 0; k < DIM; k += 4) {
        float4 vi = *reinterpret_cast<const float4*>(&xi[k]);
        float4 vj = *reinterpret_cast<const float4*>(&xj[k]);
        dq += vi.x * vj.x + vi.y * vj.y + vi.z * vj.z + vi.w * vj.w;
    }
    // bf16-consistent diagonal + positive-pair terms (same inputs the GEMM saw)
    float dii = 0.f, dpp = 0.f;
    const __nv_bfloat16* hi = g_Xh + (size_t)i   * DIM;
    const __nv_bfloat16* hp = g_Xh + (size_t)pos * DIM;
    #pragma unroll
    for (int k = 0; k < DIM; k += 2) {
        float2 a2 = __bfloat1622float2(*reinterpret_cast<const __nv_bfloat162*>(&hi[k]));
        float2 b2 = __bfloat1622float2(*reinterpret_cast<const __nv_bfloat162*>(&hp[k]));
        dii += a2.x * a2.x + a2.y * a2.y;
        dpp += a2.x * b2.x + a2.y * b2.y;
    }

    float masked = R - __expf(2.f * dii) - __expf(2.f * dpp);
    g_loss[i] = logf(masked) - 2.0f * dq;
}

// ---------------------------------------------------------------------------
// 4) Final reduce: mean over 2B rows.
// ---------------------------------------------------------------------------
__global__ void __launch_bounds__(256) reduce_kernel(float* __restrict__ out) {
    __shared__ float sm[256];
    float s = 0.f;
    for (int i = threadIdx.x; i < TWO_B; i += 256) s += g_loss[i];
    sm[threadIdx.x] = s;
    __syncthreads();
    #pragma unroll
    for (int off = 128; off > 0; off >>= 1) {
        if (threadIdx.x < off) sm[threadIdx.x] += sm[threadIdx.x + off];
        __syncthreads();
    }
    if (threadIdx.x == 0) out[0] = sm[0] / (float)TWO_B;
}

// ---------------------------------------------------------------------------
extern "C" void kernel_launch(void* const* d_in, const int* in_sizes, int n_in,
                              void* d_out, int out_size) {
    const float* E      = (const float*)d_in[0];
    const int*   labels = (const int*)d_in[1];
    float* out = (float*)d_out;

    cudaFuncSetAttribute(gemm_sym_kernel,
                         cudaFuncAttributeMaxDynamicSharedMemorySize, SM_TOT);

    normalize_kernel<<<TWO_B / 8, 256>>>(E);
    gemm_sym_kernel<<<NCTA, 256, SM_TOT>>>();
    finalize_kernel<<<TWO_B / 256, 256>>>(labels);
    reduce_kernel<<<1, 256>>>(out);
}

// round 9
// speedup vs baseline: 14.5755x; 1.0274x over previous
#include <cuda_runtime.h>
#include <cuda_bf16.h>
#include <math.h>
#include <cstdint>

// NTXent loss, 2B = 8192, D = 128.
// Symmetric bf16 HMMA GEMM over upper-triangle 128x128 blocks, strip-mined.
// bf16 inputs pre-scaled by sqrt(2*log2(e)) so acc == ex2 argument directly.
// 3 launches: normalize -> gemm -> fused finalize+reduce (last-block).

#define TWO_B   8192
#define DIM     128
#define NBLK    64
#define NCTA    288           // sum over octets o: (8-o)*8
#define NSLOT   72            // 8 row-sum slots + 64 col-sum slots
#define NFBLK   32            // finalize blocks

__device__ __nv_bfloat16 g_Xh[TWO_B * DIM];     // normalized*sqrt(C2) bf16 (MMA)
__device__ float         g_inorm[TWO_B];        // 1/||e_i||
__device__ float         g_part[NSLOT][TWO_B];  // [slot][row] partials (unused stay 0)
__device__ float         g_bpart[NFBLK];        // per-block loss partials
__device__ int           g_count;               // last-block counter (self-resetting)

// C2 = 2*log2(e); SQC2 = sqrt(C2)
#define SQC2 1.6986435838704467f

// ---------------------------------------------------------------------------
// helpers
// ---------------------------------------------------------------------------
__device__ __forceinline__ uint32_t smem_u32(const void* p) {
    uint32_t a;
    asm("{ .reg .u64 t; cvta.to.shared.u64 t, %1; cvt.u32.u64 %0, t; }" : "=r"(a) : "l"(p));
    return a;
}
__device__ __forceinline__ void cp16(uint32_t saddr, const void* g) {
    asm volatile("cp.async.cg.shared.global [%0], [%1], 16;" :: "r"(saddr), "l"(g));
}
#define CP_COMMIT() asm volatile("cp.async.commit_group;" ::: "memory")
#define CP_WAIT0()  asm volatile("cp.async.wait_group 0;" ::: "memory")

__device__ __forceinline__ void ldsm4(uint32_t* r, uint32_t addr) {
    asm volatile("ldmatrix.sync.aligned.m8n8.x4.shared.b16 {%0,%1,%2,%3}, [%4];"
                 : "=r"(r[0]), "=r"(r[1]), "=r"(r[2]), "=r"(r[3]) : "r"(addr));
}
__device__ __forceinline__ void mma16816(float* d, const uint32_t* a, uint32_t b0, uint32_t b1) {
    asm volatile("mma.sync.aligned.m16n8k16.row.col.f32.bf16.bf16.f32 "
                 "{%0,%1,%2,%3}, {%4,%5,%6,%7}, {%8,%9}, {%0,%1,%2,%3};"
                 : "+f"(d[0]), "+f"(d[1]), "+f"(d[2]), "+f"(d[3])
                 : "r"(a[0]), "r"(a[1]), "r"(a[2]), "r"(a[3]), "r"(b0), "r"(b1));
}
__device__ __forceinline__ float ex2(float x) {
    float y; asm("ex2.approx.ftz.f32 %0, %1;" : "=f"(y) : "f"(x)); return y;
}

// ---------------------------------------------------------------------------
// 1) Row-normalize -> scaled bf16 + inverse norms. One warp per row.
// ---------------------------------------------------------------------------
__global__ void __launch_bounds__(256) normalize_kernel(const float* __restrict__ E) {
    int warp = threadIdx.x >> 5, lane = threadIdx.x & 31;
    int row = blockIdx.x * 8 + warp;
    const float4 v = *reinterpret_cast<const float4*>(&E[row * DIM + lane * 4]);
    float ss = v.x * v.x + v.y * v.y + v.z * v.z + v.w * v.w;
    #pragma unroll
    for (int o = 16; o > 0; o >>= 1) ss += __shfl_xor_sync(0xffffffffu, ss, o);
    float inv = rsqrtf(fmaxf(ss, 1e-24f));
    if (lane == 0) g_inorm[row] = inv;
    float s = inv * SQC2;
    __nv_bfloat162 h0 = __float22bfloat162_rn(make_float2(v.x * s, v.y * s));
    __nv_bfloat162 h1 = __float22bfloat162_rn(make_float2(v.z * s, v.w * s));
    uint2 pk = { *reinterpret_cast<uint32_t*>(&h0), *reinterpret_cast<uint32_t*>(&h1) };
    *reinterpret_cast<uint2*>(&g_Xh[row * DIM + lane * 4]) = pk;
}

// ---------------------------------------------------------------------------
// 2) Strip-mined symmetric HMMA GEMM + exp row/col sums.
//    256 threads = 8 warps (wm 0..3 x wn 0..1); warp tile 32x64; K=128.
// ---------------------------------------------------------------------------
#define SROWB   272                        // smem row stride (17*16 B)
#define TILE_B  (128 * SROWB)              // 34816
#define SM_A    0
#define SM_B0   TILE_B
#define SM_B1   (2 * TILE_B)
#define SM_RED  (3 * TILE_B)               // colred[4][128] / rowred[2][128]
#define SM_TOT  (SM_RED + 4 * 128 * 4)

__global__ void __launch_bounds__(256, 2) gemm_sym_kernel() {
    extern __shared__ __align__(16) char smem[];
    const uint32_t sb = smem_u32(smem);
    const int tid  = threadIdx.x;
    const int lane = tid & 31;
    const int warp = tid >> 5;
    const int wm = warp >> 1;              // 0..3
    const int wn = warp & 1;               // 0..1

    // decode blockIdx -> (I, c): octet o of I, chunks c = o..7
    int t = blockIdx.x, o = 0;
    for (;;) { int n = (8 - o) * 8; if (t < n) break; t -= n; ++o; }
    const int c  = o + (t >> 3);
    const int I  = 8 * o + (t & 7);
    const int J0 = max(8 * c, I);
    const int L  = 8 * c + 8 - J0;         // strip length (1..8)
    const int rowBase = I * 128;

    const char* __restrict__ Xb = reinterpret_cast<const char*>(g_Xh);

    auto loadTile = [&](uint32_t dst, int gRow) {
        #pragma unroll
        for (int i = 0; i < 8; ++i) {
            int f = tid + i * 256;
            int r = f >> 4, cc = (f & 15) << 4;
            cp16(dst + r * SROWB + cc, Xb + (size_t)(gRow + r) * 256 + cc);
        }
    };

    loadTile(sb + SM_A, rowBase);
    loadTile(sb + SM_B0, J0 * 128);
    CP_COMMIT();

    const uint32_t aBase = sb + SM_A + (uint32_t)(wm * 32 + (lane & 15)) * SROWB + ((lane >> 4) << 4);
    const uint32_t bOff  = (uint32_t)(wn * 64 + (lane & 15)) * SROWB + ((lane >> 4) << 4);

    float rs[4] = {0.f, 0.f, 0.f, 0.f};    // strip-accumulated row sums
    float* colred = reinterpret_cast<float*>(smem + SM_RED);   // [4][128]

    for (int k = 0; k < L; ++k) {
        const int J = J0 + k;
        CP_WAIT0();
        __syncthreads();   // B(k) resident; prev tile's colred reads done

        if (k + 1 < L) {
            loadTile(sb + (((k + 1) & 1) ? SM_B1 : SM_B0), (J + 1) * 128);
            CP_COMMIT();
        }

        const uint32_t bBase = sb + ((k & 1) ? SM_B1 : SM_B0) + bOff;

        float acc[2][8][4];
        #pragma unroll
        for (int m = 0; m < 2; ++m)
            #pragma unroll
            for (int n = 0; n < 8; ++n)
                #pragma unroll
                for (int u = 0; u < 4; ++u) acc[m][n][u] = 0.f;

        #pragma unroll
        for (int ks = 0; ks < 8; ++ks) {
            uint32_t a[2][4], b[4][4];
            #pragma unroll
            for (int m = 0; m < 2; ++m)
                ldsm4(a[m], aBase + m * (16 * SROWB) + ks * 32);
            #pragma unroll
            for (int n4 = 0; n4 < 4; ++n4)
                ldsm4(b[n4], bBase + n4 * (16 * SROWB) + ks * 32);
            #pragma unroll
            for (int m = 0; m < 2; ++m)
                #pragma unroll
                for (int n4 = 0; n4 < 4; ++n4) {
                    mma16816(acc[m][n4 * 2 + 0], a[m], b[n4][0], b[n4][2]);
                    mma16816(acc[m][n4 * 2 + 1], a[m], b[n4][1], b[n4][3]);
                }
        }

        // epilogue: e = ex2(acc) (scale folded into inputs)
        float cs[8][2];
        #pragma unroll
        for (int n = 0; n < 8; ++n) { cs[n][0] = 0.f; cs[n][1] = 0.f; }

        #pragma unroll
        for (int m = 0; m < 2; ++m)
            #pragma unroll
            for (int n = 0; n < 8; ++n)
                #pragma unroll
                for (int u = 0; u < 4; ++u) {
                    float e = ex2(acc[m][n][u]);
                    rs[m * 2 + (u >> 1)] += e;
                    cs[n][u & 1] += e;
                }

        if (J != I) {
            #pragma unroll
            for (int n = 0; n < 8; ++n)
                #pragma unroll
                for (int b = 0; b < 2; ++b) {
                    cs[n][b] += __shfl_xor_sync(0xffffffffu, cs[n][b], 4);
                    cs[n][b] += __shfl_xor_sync(0xffffffffu, cs[n][b], 8);
                    cs[n][b] += __shfl_xor_sync(0xffffffffu, cs[n][b], 16);
                }
            if (lane < 4) {
                #pragma unroll
                for (int n = 0; n < 8; ++n)
                    #pragma unroll
                    for (int b = 0; b < 2; ++b) {
                        int cc = wn * 64 + (n >> 1) * 16 + (n & 1) * 8 + lane * 2 + b;
                        colred[wm * 128 + cc] = cs[n][b];
                    }
            }
            __syncthreads();
            if (tid < 128) {
                float ct = colred[tid] + colred[128 + tid] +
                           colred[256 + tid] + colred[384 + tid];
                g_part[8 + I][J * 128 + tid] = ct;
            }
        } else {
            __syncthreads();   // keep barrier count uniform
        }
    }

    // strip row sums
    #pragma unroll
    for (int u = 0; u < 4; ++u) {
        rs[u] += __shfl_xor_sync(0xffffffffu, rs[u], 1);
        rs[u] += __shfl_xor_sync(0xffffffffu, rs[u], 2);
    }
    float* rowred = reinterpret_cast<float*>(smem + SM_RED);   // [2][128]
    __syncthreads();
    if ((lane & 3) == 0) {
        #pragma unroll
        for (int u = 0; u < 4; ++u) {
            int r = wm * 32 + (u >> 1) * 16 + (u & 1) * 8 + (lane >> 2);
            rowred[wn * 128 + r] = rs[u];
        }
    }
    __syncthreads();
    if (tid < 128)
        g_part[c][rowBase + tid] = rowred[tid] + rowred[128 + tid];
}

// ---------------------------------------------------------------------------
// 3) Fused finalize + reduce. 32 blocks x 256 threads, one row per thread.
//    Last block (atomic counter) sums the 32 block partials in fixed order.
// ---------------------------------------------------------------------------
__global__ void __launch_bounds__(256) finalize_reduce_kernel(
        const float* __restrict__ E, const int* __restrict__ labels,
        float* __restrict__ out) {
    const int i = blockIdx.x * 256 + threadIdx.x;

    float R = 0.f;
    #pragma unroll 8
    for (int s = 0; s < NSLOT; ++s) R += g_part[s][i];

    int pos = (i < TWO_B / 2) ? (i + TWO_B / 2) : (i - TWO_B / 2);
    int a = min(i, pos), b = max(i, pos);
    int l = labels[i];
    int j = l + (l >= a ? 1 : 0);
    j += (j >= b ? 1 : 0);

    // exact fp32 picked logit from raw E + inverse norms
    const float* ei = E + (size_t)i * DIM;
    const float* ej = E + (size_t)j * DIM;
    float dq = 0.f;
    #pragma unroll
    for (int k = 0; k < DIM; k += 4) {
        float4 vi = *reinterpret_cast<const float4*>(&ei[k]);
        float4 vj = *reinterpret_cast<const float4*>(&ej[k]);
        dq += vi.x * vj.x + vi.y * vj.y + vi.z * vj.z + vi.w * vj.w;
    }
    float q = 2.0f * dq * g_inorm[i] * g_inorm[j];

    // bf16-consistent diagonal + positive-pair terms (scaled values: acc == ex2 arg)
    float dii = 0.f, dpp = 0.f;
    const __nv_bfloat16* hi = g_Xh + (size_t)i   * DIM;
    const __nv_bfloat16* hp = g_Xh + (size_t)pos * DIM;
    #pragma unroll
    for (int k = 0; k < DIM; k += 2) {
        float2 a2 = __bfloat1622float2(*reinterpret_cast<const __nv_bfloat162*>(&hi[k]));
        float2 b2 = __bfloat1622float2(*reinterpret_cast<const __nv_bfloat162*>(&hp[k]));
        dii += a2.x * a2.x + a2.y * a2.y;
        dpp += a2.x * b2.x + a2.y * b2.y;
    }

    float masked = R - ex2(dii) - ex2(dpp);
    float loss = logf(masked) - q;

    // block reduce (deterministic)
    __shared__ float sm[256];
    __shared__ bool isLast;
    sm[threadIdx.x] = loss;
    __syncthreads();
    #pragma unroll
    for (int off = 128; off > 0; off >>= 1) {
        if (threadIdx.x < off) sm[threadIdx.x] += sm[threadIdx.x + off];
        __syncthreads();
    }
    if (threadIdx.x == 0) {
        g_bpart[blockIdx.x] = sm[0];
        __threadfence();
        int cdone = atomicAdd(&g_count, 1);
        isLast = (cdone == NFBLK - 1);
    }
    __syncthreads();
    if (isLast && threadIdx.x == 0) {
        float s = 0.f;
        #pragma unroll
        for (int bb = 0; bb < NFBLK; ++bb) s += g_bpart[bb];
        out[0] = s / (float)TWO_B;
        g_count = 0;                      // reset for next graph replay
    }
}

// ---------------------------------------------------------------------------
extern "C" void kernel_launch(void* const* d_in, const int* in_sizes, int n_in,
                              void* d_out, int out_size) {
    const float* E      = (const float*)d_in[0];
    const int*   labels = (const int*)d_in[1];
    float* out = (float*)d_out;

    cudaFuncSetAttribute(gemm_sym_kernel,
                         cudaFuncAttributeMaxDynamicSharedMemorySize, SM_TOT);

    normalize_kernel<<<TWO_B / 8, 256>>>(E);
    gemm_sym_kernel<<<NCTA, 256, SM_TOT>>>();
    finalize_reduce_kernel<<<NFBLK, 256>>>(E, labels, out);
}

// round 10
// speedup vs baseline: 15.0495x; 1.0325x over previous
#include <cuda_runtime.h>
#include <cuda_fp16.h>
#include <math.h>
#include <cstdint>

// NTXent loss, 2B = 8192, D = 128.
// Symmetric fp16 HMMA GEMM (f16 accumulators) over upper-triangle 128x128
// blocks, strip-mined. Inputs pre-scaled by sqrt(2*log2(e)) so acc == ex2 arg.
// 3 launches: normalize -> gemm -> fused finalize+reduce (last-block).

#define TWO_B   8192
#define DIM     128
#define NBLK    64
#define NCTA    288           // sum over octets o: (8-o)*8
#define NSLOT   72            // 8 row-sum slots + 64 col-sum slots
#define NFBLK   32            // finalize blocks

__device__ __half g_Xh[TWO_B * DIM];            // normalized*sqrt(C2) fp16 (MMA)
__device__ float  g_inorm[TWO_B];               // 1/||e_i||
__device__ float  g_part[NSLOT][TWO_B];         // [slot][row] partials (unused stay 0)
__device__ float  g_bpart[NFBLK];               // per-block loss partials
__device__ int    g_count;                      // last-block counter (self-resetting)

// C2 = 2*log2(e); SQC2 = sqrt(C2)
#define SQC2 1.6986435838704467f

// ---------------------------------------------------------------------------
// helpers
// ---------------------------------------------------------------------------
__device__ __forceinline__ uint32_t smem_u32(const void* p) {
    uint32_t a;
    asm("{ .reg .u64 t; cvta.to.shared.u64 t, %1; cvt.u32.u64 %0, t; }" : "=r"(a) : "l"(p));
    return a;
}
__device__ __forceinline__ void cp16(uint32_t saddr, const void* g) {
    asm volatile("cp.async.cg.shared.global [%0], [%1], 16;" :: "r"(saddr), "l"(g));
}
#define CP_COMMIT() asm volatile("cp.async.commit_group;" ::: "memory")
#define CP_WAIT0()  asm volatile("cp.async.wait_group 0;" ::: "memory")

__device__ __forceinline__ void ldsm4(uint32_t* r, uint32_t addr) {
    asm volatile("ldmatrix.sync.aligned.m8n8.x4.shared.b16 {%0,%1,%2,%3}, [%4];"
                 : "=r"(r[0]), "=r"(r[1]), "=r"(r[2]), "=r"(r[3]) : "r"(addr));
}
// f16-accumulator HMMA: D,C are 2 b32 regs (reg g holds row-group g, 2 cols packed)
__device__ __forceinline__ void mma16816h(uint32_t* d, const uint32_t* a, uint32_t b0, uint32_t b1) {
    asm volatile("mma.sync.aligned.m16n8k16.row.col.f16.f16.f16.f16 "
                 "{%0,%1}, {%2,%3,%4,%5}, {%6,%7}, {%0,%1};"
                 : "+r"(d[0]), "+r"(d[1])
                 : "r"(a[0]), "r"(a[1]), "r"(a[2]), "r"(a[3]), "r"(b0), "r"(b1));
}
__device__ __forceinline__ uint32_t hex2(uint32_t x) {
    uint32_t y; asm("ex2.approx.f16x2 %0, %1;" : "=r"(y) : "r"(x)); return y;
}
__device__ __forceinline__ uint32_t hadd2(uint32_t a, uint32_t b) {
    uint32_t y; asm("add.rn.f16x2 %0, %1, %2;" : "=r"(y) : "r"(a), "r"(b)); return y;
}
__device__ __forceinline__ float2 h2f(uint32_t r) {
    __half2 h = *reinterpret_cast<__half2*>(&r);
    return __half22float2(h);
}
__device__ __forceinline__ float ex2f(float x) {
    float y; asm("ex2.approx.ftz.f32 %0, %1;" : "=f"(y) : "f"(x)); return y;
}

// ---------------------------------------------------------------------------
// 1) Row-normalize -> scaled fp16 + inverse norms. One warp per row.
// ---------------------------------------------------------------------------
__global__ void __launch_bounds__(256) normalize_kernel(const float* __restrict__ E) {
    int warp = threadIdx.x >> 5, lane = threadIdx.x & 31;
    int row = blockIdx.x * 8 + warp;
    const float4 v = *reinterpret_cast<const float4*>(&E[row * DIM + lane * 4]);
    float ss = v.x * v.x + v.y * v.y + v.z * v.z + v.w * v.w;
    #pragma unroll
    for (int o = 16; o > 0; o >>= 1) ss += __shfl_xor_sync(0xffffffffu, ss, o);
    float inv = rsqrtf(fmaxf(ss, 1e-24f));
    if (lane == 0) g_inorm[row] = inv;
    float s = inv * SQC2;
    __half2 h0 = __float22half2_rn(make_float2(v.x * s, v.y * s));
    __half2 h1 = __float22half2_rn(make_float2(v.z * s, v.w * s));
    uint2 pk = { *reinterpret_cast<uint32_t*>(&h0), *reinterpret_cast<uint32_t*>(&h1) };
    *reinterpret_cast<uint2*>(&g_Xh[row * DIM + lane * 4]) = pk;
}

// ---------------------------------------------------------------------------
// 2) Strip-mined symmetric HMMA GEMM (f16 acc) + exp row/col sums.
//    256 threads = 8 warps (wm 0..3 x wn 0..1); warp tile 32x64; K=128.
// ---------------------------------------------------------------------------
#define SROWB   272                        // smem row stride (17*16 B)
#define TILE_B  (128 * SROWB)              // 34816
#define SM_A    0
#define SM_B0   TILE_B
#define SM_B1   (2 * TILE_B)
#define SM_RED  (3 * TILE_B)               // colred[4][128] / rowred[2][128]
#define SM_TOT  (SM_RED + 4 * 128 * 4)

__global__ void __launch_bounds__(256, 2) gemm_sym_kernel() {
    extern __shared__ __align__(16) char smem[];
    const uint32_t sb = smem_u32(smem);
    const int tid  = threadIdx.x;
    const int lane = tid & 31;
    const int warp = tid >> 5;
    const int wm = warp >> 1;              // 0..3
    const int wn = warp & 1;               // 0..1

    // decode blockIdx -> (I, c): octet o of I, chunks c = o..7
    int t = blockIdx.x, o = 0;
    for (;;) { int n = (8 - o) * 8; if (t < n) break; t -= n; ++o; }
    const int c  = o + (t >> 3);
    const int I  = 8 * o + (t & 7);
    const int J0 = max(8 * c, I);
    const int L  = 8 * c + 8 - J0;         // strip length (1..8)
    const int rowBase = I * 128;

    const char* __restrict__ Xb = reinterpret_cast<const char*>(g_Xh);

    auto loadTile = [&](uint32_t dst, int gRow) {
        #pragma unroll
        for (int i = 0; i < 8; ++i) {
            int f = tid + i * 256;
            int r = f >> 4, cc = (f & 15) << 4;
            cp16(dst + r * SROWB + cc, Xb + (size_t)(gRow + r) * 256 + cc);
        }
    };

    loadTile(sb + SM_A, rowBase);
    loadTile(sb + SM_B0, J0 * 128);
    CP_COMMIT();

    const uint32_t aBase = sb + SM_A + (uint32_t)(wm * 32 + (lane & 15)) * SROWB + ((lane >> 4) << 4);
    const uint32_t bOff  = (uint32_t)(wn * 64 + (lane & 15)) * SROWB + ((lane >> 4) << 4);

    float rs32[4] = {0.f, 0.f, 0.f, 0.f};  // strip row sums (fp32)
    float* colred = reinterpret_cast<float*>(smem + SM_RED);   // [4][128]

    for (int k = 0; k < L; ++k) {
        const int J = J0 + k;
        CP_WAIT0();
        __syncthreads();   // B(k) resident; prev tile's colred reads done

        if (k + 1 < L) {
            loadTile(sb + (((k + 1) & 1) ? SM_B1 : SM_B0), (J + 1) * 128);
            CP_COMMIT();
        }

        const uint32_t bBase = sb + ((k & 1) ? SM_B1 : SM_B0) + bOff;

        uint32_t acc[2][8][2];             // f16x2 accumulators
        #pragma unroll
        for (int m = 0; m < 2; ++m)
            #pragma unroll
            for (int n = 0; n < 8; ++n) { acc[m][n][0] = 0u; acc[m][n][1] = 0u; }

        #pragma unroll
        for (int ks = 0; ks < 8; ++ks) {
            uint32_t a[2][4], b[4][4];
            #pragma unroll
            for (int m = 0; m < 2; ++m)
                ldsm4(a[m], aBase + m * (16 * SROWB) + ks * 32);
            #pragma unroll
            for (int n4 = 0; n4 < 4; ++n4)
                ldsm4(b[n4], bBase + n4 * (16 * SROWB) + ks * 32);
            #pragma unroll
            for (int m = 0; m < 2; ++m)
                #pragma unroll
                for (int n4 = 0; n4 < 4; ++n4) {
                    mma16816h(acc[m][n4 * 2 + 0], a[m], b[n4][0], b[n4][2]);
                    mma16816h(acc[m][n4 * 2 + 1], a[m], b[n4][1], b[n4][3]);
                }
        }

        // epilogue: packed e = ex2(acc); row sums + column sums
        uint32_t cs[8];
        #pragma unroll
        for (int n = 0; n < 8; ++n) cs[n] = 0u;

        #pragma unroll
        for (int m = 0; m < 2; ++m) {
            uint32_t rsp[2] = {0u, 0u};    // packed per row-group
            #pragma unroll
            for (int n = 0; n < 8; ++n) {
                uint32_t e0 = hex2(acc[m][n][0]);
                uint32_t e1 = hex2(acc[m][n][1]);
                rsp[0] = hadd2(rsp[0], e0);
                rsp[1] = hadd2(rsp[1], e1);
                cs[n] = hadd2(cs[n], hadd2(e0, e1));
            }
            #pragma unroll
            for (int g = 0; g < 2; ++g) {
                float2 f = h2f(rsp[g]);
                rs32[m * 2 + g] += f.x + f.y;
            }
        }

        if (J != I) {
            // column sums: combine the 8 row-groups within each warp (packed)
            #pragma unroll
            for (int n = 0; n < 8; ++n) {
                cs[n] = hadd2(cs[n], __shfl_xor_sync(0xffffffffu, cs[n], 4));
                cs[n] = hadd2(cs[n], __shfl_xor_sync(0xffffffffu, cs[n], 8));
                cs[n] = hadd2(cs[n], __shfl_xor_sync(0xffffffffu, cs[n], 16));
            }
            if (lane < 4) {
                #pragma unroll
                for (int n = 0; n < 8; ++n) {
                    int cc = wn * 64 + (n >> 1) * 16 + (n & 1) * 8 + lane * 2;
                    float2 f = h2f(cs[n]);
                    *reinterpret_cast<float2*>(&colred[wm * 128 + cc]) = f;
                }
            }
            __syncthreads();
            if (tid < 128) {
                float ct = colred[tid] + colred[128 + tid] +
                           colred[256 + tid] + colred[384 + tid];
                g_part[8 + I][J * 128 + tid] = ct;
            }
        } else {
            __syncthreads();   // keep barrier count uniform
        }
    }

    // strip row sums
    #pragma unroll
    for (int u = 0; u < 4; ++u) {
        rs32[u] += __shfl_xor_sync(0xffffffffu, rs32[u], 1);
        rs32[u] += __shfl_xor_sync(0xffffffffu, rs32[u], 2);
    }
    float* rowred = reinterpret_cast<float*>(smem + SM_RED);   // [2][128]
    __syncthreads();
    if ((lane & 3) == 0) {
        #pragma unroll
        for (int u = 0; u < 4; ++u) {
            int r = wm * 32 + (u >> 1) * 16 + (u & 1) * 8 + (lane >> 2);
            rowred[wn * 128 + r] = rs32[u];
        }
    }
    __syncthreads();
    if (tid < 128)
        g_part[c][rowBase + tid] = rowred[tid] + rowred[128 + tid];
}

// ---------------------------------------------------------------------------
// 3) Fused finalize + reduce. 32 blocks x 256 threads, one row per thread.
// ---------------------------------------------------------------------------
__global__ void __launch_bounds__(256) finalize_reduce_kernel(
        const float* __restrict__ E, const int* __restrict__ labels,
        float* __restrict__ out) {
    const int i = blockIdx.x * 256 + threadIdx.x;

    float R = 0.f;
    #pragma unroll 8
    for (int s = 0; s < NSLOT; ++s) R += g_part[s][i];

    int pos = (i < TWO_B / 2) ? (i + TWO_B / 2) : (i - TWO_B / 2);
    int a = min(i, pos), b = max(i, pos);
    int l = labels[i];
    int j = l + (l >= a ? 1 : 0);
    j += (j >= b ? 1 : 0);

    // exact fp32 picked logit from raw E + inverse norms
    const float* ei = E + (size_t)i * DIM;
    const float* ej = E + (size_t)j * DIM;
    float dq = 0.f;
    #pragma unroll
    for (int k = 0; k < DIM; k += 4) {
        float4 vi = *reinterpret_cast<const float4*>(&ei[k]);
        float4 vj = *reinterpret_cast<const float4*>(&ej[k]);
        dq += vi.x * vj.x + vi.y * vj.y + vi.z * vj.z + vi.w * vj.w;
    }
    float q = 2.0f * dq * g_inorm[i] * g_inorm[j];

    // fp16-consistent diagonal + positive-pair terms (scaled: acc == ex2 arg)
    float dii = 0.f, dpp = 0.f;
    const __half* hi = g_Xh + (size_t)i   * DIM;
    const __half* hp = g_Xh + (size_t)pos * DIM;
    #pragma unroll
    for (int k = 0; k < DIM; k += 2) {
        float2 a2 = __half22float2(*reinterpret_cast<const __half2*>(&hi[k]));
        float2 b2 = __half22float2(*reinterpret_cast<const __half2*>(&hp[k]));
        dii += a2.x * a2.x + a2.y * a2.y;
        dpp += a2.x * b2.x + a2.y * b2.y;
    }

    float masked = R - ex2f(dii) - ex2f(dpp);
    float loss = logf(masked) - q;

    // block reduce (deterministic) + last-block combine
    __shared__ float sm[256];
    __shared__ bool isLast;
    sm[threadIdx.x] = loss;
    __syncthreads();
    #pragma unroll
    for (int off = 128; off > 0; off >>= 1) {
        if (threadIdx.x < off) sm[threadIdx.x] += sm[threadIdx.x + off];
        __syncthreads();
    }
    if (threadIdx.x == 0) {
        g_bpart[blockIdx.x] = sm[0];
        __threadfence();
        int cdone = atomicAdd(&g_count, 1);
        isLast = (cdone == NFBLK - 1);
    }
    __syncthreads();
    if (isLast && threadIdx.x == 0) {
        float s = 0.f;
        #pragma unroll
        for (int bb = 0; bb < NFBLK; ++bb) s += g_bpart[bb];
        out[0] = s / (float)TWO_B;
        g_count = 0;                      // reset for next graph replay
    }
}

// ---------------------------------------------------------------------------
extern "C" void kernel_launch(void* const* d_in, const int* in_sizes, int n_in,
                              void* d_out, int out_size) {
    const float* E      = (const float*)d_in[0];
    const int*   labels = (const int*)d_in[1];
    float* out = (float*)d_out;

    cudaFuncSetAttribute(gemm_sym_kernel,
                         cudaFuncAttributeMaxDynamicSharedMemorySize, SM_TOT);

    normalize_kernel<<<TWO_B / 8, 256>>>(E);
    gemm_sym_kernel<<<NCTA, 256, SM_TOT>>>();
    finalize_reduce_kernel<<<NFBLK, 256>>>(E, labels, out);
}